// round 4
// baseline (speedup 1.0000x reference)
#include <cuda_runtime.h>
#include <cuda_bf16.h>
#include <cstdint>
#include <math.h>

#define Nn 32
#define Cc 256
#define ICc 128
#define Hh 32
#define Ww 32
#define Ll 1024
#define DA 9216
#define DOUT 131072
#define EPSf 1e-5f

// ---------------- scratch ----------------------------------------------------
__device__ float g_qt[Nn * Ll * ICc];     // [n][l][o]
__device__ float g_kt[Nn * Ll * ICc];     // [n][l][o]
__device__ float g_f[Nn * DA];
__device__ float g_h1[Nn * Cc];
__device__ float g_h2[Nn * DOUT];         // [n][m]
__device__ float g_stats[Nn * 2];         // LN2 sums
__device__ float g_stats1[Nn * 2];        // LN1 sums

// ---------------- mma.sync helpers -------------------------------------------
__device__ __forceinline__ uint32_t s2u(const void* p) {
    uint32_t a;
    asm("{ .reg .u64 t; cvta.to.shared.u64 t, %1; cvt.u32.u64 %0, t; }" : "=r"(a) : "l"(p));
    return a;
}
#define SZ(o) ((uint32_t)(o) ^ ((((uint32_t)(o)) >> 3) & 0x30))

__device__ __forceinline__ void ldsm4(uint32_t* r, uint32_t a) {
    asm volatile("ldmatrix.sync.aligned.m8n8.x4.shared.b16 {%0,%1,%2,%3}, [%4];"
                 : "=r"(r[0]), "=r"(r[1]), "=r"(r[2]), "=r"(r[3]) : "r"(a));
}
__device__ __forceinline__ void mma16816(float* d, const uint32_t* a, uint32_t b0, uint32_t b1) {
    asm volatile(
        "mma.sync.aligned.m16n8k16.row.col.f32.bf16.bf16.f32 "
        "{%0,%1,%2,%3}, {%4,%5,%6,%7}, {%8,%9}, {%0,%1,%2,%3};"
        : "+f"(d[0]), "+f"(d[1]), "+f"(d[2]), "+f"(d[3])
        : "r"(a[0]), "r"(a[1]), "r"(a[2]), "r"(a[3]), "r"(b0), "r"(b1));
}

__device__ __forceinline__ uint32_t bf2u(__nv_bfloat16 a, __nv_bfloat16 b) {
    return (uint32_t)__bfloat16_as_ushort(a) | ((uint32_t)__bfloat16_as_ushort(b) << 16);
}
__device__ __forceinline__ void split2(float a, float b, uint32_t& hi, uint32_t& lo) {
    __nv_bfloat16 ha = __float2bfloat16(a), hb = __float2bfloat16(b);
    __nv_bfloat16 la = __float2bfloat16(a - __bfloat162float(ha));
    __nv_bfloat16 lb = __float2bfloat16(b - __bfloat162float(hb));
    hi = bf2u(ha, hb);
    lo = bf2u(la, lb);
}

// 3-pass hi/lo MMA over one K=32 chunk; warp tile 32x64.
__device__ __forceinline__ void chunk_128x128(float (&acc)[2][8][4], uint32_t base,
                                              const uint32_t (&aoff)[2][2],
                                              const uint32_t (&boff)[4][2],
                                              uint32_t aLo, uint32_t bLo) {
#pragma unroll
    for (int ks = 0; ks < 2; ks++) {
        uint32_t ah0[4], ah1[4], al0[4], al1[4];
        ldsm4(ah0, base + aoff[0][ks]);
        ldsm4(ah1, base + aoff[1][ks]);
        ldsm4(al0, base + aoff[0][ks] + aLo);
        ldsm4(al1, base + aoff[1][ks] + aLo);
#pragma unroll
        for (int p = 0; p < 4; p++) {
            uint32_t bh[4], bl[4];
            ldsm4(bh, base + boff[p][ks]);
            ldsm4(bl, base + boff[p][ks] + bLo);
            mma16816(acc[0][2 * p],     ah0, bh[0], bh[1]);
            mma16816(acc[0][2 * p + 1], ah0, bh[2], bh[3]);
            mma16816(acc[1][2 * p],     ah1, bh[0], bh[1]);
            mma16816(acc[1][2 * p + 1], ah1, bh[2], bh[3]);
            mma16816(acc[0][2 * p],     ah0, bl[0], bl[1]);
            mma16816(acc[0][2 * p + 1], ah0, bl[2], bl[3]);
            mma16816(acc[1][2 * p],     ah1, bl[0], bl[1]);
            mma16816(acc[1][2 * p + 1], ah1, bl[2], bl[3]);
            mma16816(acc[0][2 * p],     al0, bh[0], bh[1]);
            mma16816(acc[0][2 * p + 1], al0, bh[2], bh[3]);
            mma16816(acc[1][2 * p],     al1, bh[0], bh[1]);
            mma16816(acc[1][2 * p + 1], al1, bh[2], bh[3]);
        }
    }
}
// block tile 256x32, warp tile 32x32
__device__ __forceinline__ void chunk_256x32(float (&acc)[2][4][4], uint32_t base,
                                             const uint32_t (&aoff)[2][2],
                                             const uint32_t (&boff)[2][2],
                                             uint32_t aLo, uint32_t bLo) {
#pragma unroll
    for (int ks = 0; ks < 2; ks++) {
        uint32_t ah0[4], ah1[4], al0[4], al1[4];
        ldsm4(ah0, base + aoff[0][ks]);
        ldsm4(ah1, base + aoff[1][ks]);
        ldsm4(al0, base + aoff[0][ks] + aLo);
        ldsm4(al1, base + aoff[1][ks] + aLo);
#pragma unroll
        for (int p = 0; p < 2; p++) {
            uint32_t bh[4], bl[4];
            ldsm4(bh, base + boff[p][ks]);
            ldsm4(bl, base + boff[p][ks] + bLo);
            mma16816(acc[0][2 * p],     ah0, bh[0], bh[1]);
            mma16816(acc[0][2 * p + 1], ah0, bh[2], bh[3]);
            mma16816(acc[1][2 * p],     ah1, bh[0], bh[1]);
            mma16816(acc[1][2 * p + 1], ah1, bh[2], bh[3]);
            mma16816(acc[0][2 * p],     ah0, bl[0], bl[1]);
            mma16816(acc[0][2 * p + 1], ah0, bl[2], bl[3]);
            mma16816(acc[1][2 * p],     ah1, bl[0], bl[1]);
            mma16816(acc[1][2 * p + 1], ah1, bl[2], bl[3]);
            mma16816(acc[0][2 * p],     al0, bh[0], bh[1]);
            mma16816(acc[0][2 * p + 1], al0, bh[2], bh[3]);
            mma16816(acc[1][2 * p],     al1, bh[0], bh[1]);
            mma16816(acc[1][2 * p + 1], al1, bh[2], bh[3]);
        }
    }
}

__device__ __forceinline__ void mk_aoff(uint32_t (&aoff)[2][2], int m_off, int lane,
                                        uint32_t planeA) {
    int sub = lane >> 3, rr = lane & 7;
#pragma unroll
    for (int mi = 0; mi < 2; mi++)
#pragma unroll
        for (int ks = 0; ks < 2; ks++) {
            int row = m_off + mi * 16 + (sub & 1) * 8 + rr;
            int byte = ks * 32 + (sub >> 1) * 16;
            aoff[mi][ks] = planeA + SZ(row * 64 + byte);
        }
}
template <int NP>
__device__ __forceinline__ void mk_boff(uint32_t (&boff)[NP][2], int n_off, int lane,
                                        uint32_t planeB) {
    int sub = lane >> 3, rr = lane & 7;
#pragma unroll
    for (int p = 0; p < NP; p++)
#pragma unroll
        for (int ks = 0; ks < 2; ks++) {
            int row = n_off + p * 16 + (sub >> 1) * 8 + rr;
            int byte = ks * 32 + (sub & 1) * 16;
            boff[p][ks] = planeB + SZ(row * 64 + byte);
        }
}

// ====================== K1: FUSED q+k conv ===================================
// Block tile: 64 l-rows; warps 0-3 -> q (D = x^T wq^T), warps 4-7 -> k.
// planes per buf: AH 0 (4K) | AL 4096 | BqH 8192 (8K) | BqL 16384 | BkH 24576 | BkL 32768
#define QK_BUF 40960
#define QK_SMEM (2 * QK_BUF)
__global__ void __launch_bounds__(256) k_qk_mma(const float* __restrict__ x,
                                                const float* __restrict__ wq,
                                                const float* __restrict__ wk) {
    extern __shared__ char sm[];
    const int lt = blockIdx.x, n = blockIdx.y;
    const int l0 = lt * 64;
    uint32_t sb = s2u(sm);
    int t = threadIdx.x, wid = t >> 5, lane = t & 31;
    int isK = wid >> 2;
    int w4 = wid & 3;
    int wm = w4 >> 1, wn = w4 & 1;
    int gid = lane >> 2, tig = lane & 3;

    uint32_t aoff[2][2], boff[4][2];
    mk_aoff(aoff, wm * 32, lane, 0u);
    mk_boff<4>(boff, wn * 64, lane, isK ? 24576u : 8192u);

    float acc[2][8][4];
#pragma unroll
    for (int i = 0; i < 2; i++)
#pragma unroll
        for (int j = 0; j < 8; j++)
#pragma unroll
            for (int q = 0; q < 4; q++) acc[i][j][q] = 0.f;

    const int la = t & 63, cg = t >> 6;   // cg 0..3 -> 8 c each
    const float* xc = x + (size_t)n * Cc * Ll + l0 + la;

    float sa[8];
    float4 sbq[4], sbk[4];

#define QK_LOAD(c0) {                                                          \
    _Pragma("unroll")                                                          \
    for (int j = 0; j < 8; j++) sa[j] = xc[(size_t)((c0) + cg * 8 + j) * Ll];  \
    _Pragma("unroll")                                                          \
    for (int it = 0; it < 4; it++) {                                           \
        int idx = it * 256 + t;                                                \
        int row = idx >> 3, c4 = (idx & 7) * 4;                                \
        sbq[it] = *(const float4*)&wq[(size_t)row * Cc + (c0) + c4];           \
        sbk[it] = *(const float4*)&wk[(size_t)row * Cc + (c0) + c4];           \
    } }
#define QK_STORE(bsel) {                                                       \
    uint32_t bo = (bsel) * QK_BUF;                                             \
    {                                                                          \
        uint32_t h0, lo0, h1, lo1;                                             \
        split2(sa[0], sa[1], h0, lo0);                                         \
        split2(sa[2], sa[3], h1, lo1);                                         \
        uint32_t off = SZ(la * 64 + cg * 16);                                  \
        *(uint2*)(sm + bo + off)        = make_uint2(h0, h1);                  \
        *(uint2*)(sm + bo + 4096 + off) = make_uint2(lo0, lo1);                \
        split2(sa[4], sa[5], h0, lo0);                                         \
        split2(sa[6], sa[7], h1, lo1);                                         \
        off = SZ(la * 64 + cg * 16 + 8);                                       \
        *(uint2*)(sm + bo + off)        = make_uint2(h0, h1);                  \
        *(uint2*)(sm + bo + 4096 + off) = make_uint2(lo0, lo1);                \
    }                                                                          \
    _Pragma("unroll")                                                          \
    for (int it = 0; it < 4; it++) {                                           \
        int idx = it * 256 + t;                                                \
        int row = idx >> 3, c4 = (idx & 7) * 4;                                \
        uint32_t off = SZ(row * 64 + c4 * 2);                                  \
        uint32_t h0, lo0, h1, lo1;                                             \
        split2(sbq[it].x, sbq[it].y, h0, lo0);                                 \
        split2(sbq[it].z, sbq[it].w, h1, lo1);                                 \
        *(uint2*)(sm + bo + 8192 + off)  = make_uint2(h0, h1);                 \
        *(uint2*)(sm + bo + 16384 + off) = make_uint2(lo0, lo1);               \
        split2(sbk[it].x, sbk[it].y, h0, lo0);                                 \
        split2(sbk[it].z, sbk[it].w, h1, lo1);                                 \
        *(uint2*)(sm + bo + 24576 + off) = make_uint2(h0, h1);                 \
        *(uint2*)(sm + bo + 32768 + off) = make_uint2(lo0, lo1);               \
    } }

    QK_LOAD(0);
    QK_STORE(0);
    __syncthreads();
#pragma unroll 1
    for (int c = 0; c < 8; c++) {
        if (c + 1 < 8) QK_LOAD((c + 1) * 32);
        chunk_128x128(acc, sb + (c & 1) * QK_BUF, aoff, boff, 4096u, 8192u);
        if (c + 1 < 8) QK_STORE((c + 1) & 1);
        __syncthreads();
    }
    float* outp = isK ? g_kt : g_qt;
#pragma unroll
    for (int mi = 0; mi < 2; mi++)
#pragma unroll
        for (int r2 = 0; r2 < 2; r2++) {
            int l = l0 + wm * 32 + mi * 16 + gid + r2 * 8;
            float* op = outp + ((size_t)(n << 10) + l) * ICc + wn * 64;
#pragma unroll
            for (int nj = 0; nj < 8; nj++)
                *(float2*)&op[nj * 8 + tig * 2] =
                    make_float2(acc[mi][nj][r2 * 2], acc[mi][nj][r2 * 2 + 1]);
        }
}

// ====================== K2: local attention + LN1 stats ======================
__global__ void __launch_bounds__(256) k_attn() {
    int wid = threadIdx.x >> 5;
    int gw = blockIdx.x * 8 + wid;
    int lane = threadIdx.x & 31;
    int n = gw >> 10;
    int l = gw & 1023;
    int h = l >> 5, w = l & 31;
    const float* qp = g_qt + ((size_t)(n << 10) + l) * ICc;
    float4 qv = *(const float4*)&qp[lane * 4];
    float acc[9];
#pragma unroll
    for (int r = 0; r < 9; r++) {
        int hh = h + r / 3 - 1;
        int ww = w + r % 3 - 1;
        float s = 0.f;
        if (hh >= 0 && hh < Hh && ww >= 0 && ww < Ww) {
            const float* kp = g_kt + ((size_t)(n << 10) + (hh << 5) + ww) * ICc;
            float4 kv = *(const float4*)&kp[lane * 4];
            s = qv.x * kv.x + qv.y * kv.y + qv.z * kv.z + qv.w * kv.w;
        }
#pragma unroll
        for (int off = 16; off; off >>= 1) s += __shfl_xor_sync(0xffffffffu, s, off);
        acc[r] = s;
    }
    float val = 0.f;
#pragma unroll
    for (int r = 0; r < 9; r++)
        if (lane == r) val = acc[r];
    if (lane < 9) g_f[(size_t)n * DA + lane * Ll + l] = 2.f * val;

    // LN1 stats: all lanes hold the 9 reduced values
    __shared__ float bs[16];
    if (lane == 0) {
        float s = 0.f, s2 = 0.f;
#pragma unroll
        for (int r = 0; r < 9; r++) {
            float v = 2.f * acc[r];
            s += v; s2 += v * v;
        }
        bs[wid] = s;
        bs[8 + wid] = s2;
    }
    __syncthreads();
    if (threadIdx.x == 0) {
        float S = 0.f, S2 = 0.f;
#pragma unroll
        for (int i = 0; i < 8; i++) { S += bs[i]; S2 += bs[8 + i]; }
        atomicAdd(&g_stats1[n * 2],     S);
        atomicAdd(&g_stats1[n * 2 + 1], S2);
    }
}

// ---------------- init --------------------------------------------------------
__global__ void k_init(const float* __restrict__ b1) {
    int t = blockIdx.x * blockDim.x + threadIdx.x;
    if (t < Nn * Cc) g_h1[t] = b1[t & 255];
    if (t < Nn * 2) { g_stats[t] = 0.f; g_stats1[t] = 0.f; }
}

// ---------------- LN1: normalize only (stats from k_attn) --------------------
__global__ void __launch_bounds__(256) k_ln1(const float* __restrict__ g1,
                                             const float* __restrict__ be1) {
    int sl = blockIdx.x, n = blockIdx.y, t = threadIdx.x;
    float mu = g_stats1[n * 2] * (1.f / DA);
    float rs = rsqrtf(g_stats1[n * 2 + 1] * (1.f / DA) - mu * mu + EPSf);
    float4* fp4 = (float4*)(g_f + (size_t)n * DA);
    const float4* g4 = (const float4*)g1;
    const float4* b4 = (const float4*)be1;
    int base = sl * 576;   // 2304 float4 / 4 slices
    for (int j = base + t; j < base + 576; j += 256) {
        float4 v = fp4[j];
        float4 gg = g4[j], bb = b4[j];
        v.x = (v.x - mu) * rs * gg.x + bb.x;
        v.y = (v.y - mu) * rs * gg.y + bb.y;
        v.z = (v.z - mu) * rs * gg.z + bb.z;
        v.w = (v.w - mu) * rs * gg.w + bb.w;
        fp4[j] = v;
    }
}

// ---------------- FFN1 split-K ------------------------------------------------
__global__ void __launch_bounds__(256) k_ffn1(const float* __restrict__ w1) {
    int c0 = blockIdx.x * 16;
    int jbase = blockIdx.y * 384;
    __shared__ float fs[32][33];
    __shared__ float ws[16][33];
    int t = threadIdx.x;
    int n = t & 31, cg = t >> 5;
    int c = c0 + cg * 2;
    float acc0 = 0.f, acc1 = 0.f;
    for (int jc = 0; jc < 12; jc++) {
        int j0 = jbase + jc * 32;
        {
            int nn = t >> 3, jj = (t & 7) * 4;
            float4 v = *(const float4*)&g_f[(size_t)nn * DA + j0 + jj];
            fs[nn][jj] = v.x; fs[nn][jj + 1] = v.y; fs[nn][jj + 2] = v.z; fs[nn][jj + 3] = v.w;
        }
        for (int idx = t; idx < 512; idx += 256) {
            int cl = idx >> 5, jj = idx & 31;
            ws[cl][jj] = w1[(size_t)(c0 + cl) * DA + j0 + jj];
        }
        __syncthreads();
#pragma unroll
        for (int jj = 0; jj < 32; jj++) {
            float fv = fs[n][jj];
            acc0 += fv * ws[cg * 2][jj];
            acc1 += fv * ws[cg * 2 + 1][jj];
        }
        __syncthreads();
    }
    atomicAdd(&g_h1[n * Cc + c],     acc0);
    atomicAdd(&g_h1[n * Cc + c + 1], acc1);
}

// ====================== K5: FFN2 + LN2 stats ==================================
#define F2_BUF 36864
#define F2_SMEM (2 * F2_BUF)
__global__ void __launch_bounds__(256) k_ffn2_mma(const float* __restrict__ w2,
                                                  const float* __restrict__ b2) {
    extern __shared__ char sm[];
    const int m0 = blockIdx.x * 256;
    uint32_t sb = s2u(sm);
    int t = threadIdx.x, wid = t >> 5, lane = t & 31;
    int gid = lane >> 2, tig = lane & 3;

    uint32_t aoff[2][2], boff[2][2];
    mk_aoff(aoff, wid * 32, lane, 0u);
    mk_boff<2>(boff, 0, lane, 32768u);

    float acc[2][4][4];
#pragma unroll
    for (int i = 0; i < 2; i++)
#pragma unroll
        for (int j = 0; j < 4; j++)
#pragma unroll
            for (int q = 0; q < 4; q++) acc[i][j][q] = 0.f;

    float4 sav[8];
    float4 sbv;

#define F2_LOAD(c0) {                                                          \
    _Pragma("unroll")                                                          \
    for (int it = 0; it < 8; it++) {                                           \
        int idx = it * 256 + t;                                                \
        int row = idx >> 3, c4 = (idx & 7) * 4;                                \
        sav[it] = *(const float4*)&w2[(size_t)(m0 + row) * Cc + (c0) + c4];    \
    }                                                                          \
    {                                                                          \
        int row = t >> 3, c4 = (t & 7) * 4;                                    \
        float4 v = *(const float4*)&g_h1[(size_t)row * Cc + (c0) + c4];        \
        v.x = fmaxf(v.x, 0.f); v.y = fmaxf(v.y, 0.f);                          \
        v.z = fmaxf(v.z, 0.f); v.w = fmaxf(v.w, 0.f);                          \
        sbv = v;                                                               \
    } }
#define F2_STORE(bsel) {                                                       \
    uint32_t bo = (bsel) * F2_BUF;                                             \
    _Pragma("unroll")                                                          \
    for (int it = 0; it < 8; it++) {                                           \
        int idx = it * 256 + t;                                                \
        int row = idx >> 3, c4 = (idx & 7) * 4;                                \
        uint32_t h0, lo0, h1, lo1;                                             \
        split2(sav[it].x, sav[it].y, h0, lo0);                                 \
        split2(sav[it].z, sav[it].w, h1, lo1);                                 \
        uint32_t off = SZ(row * 64 + c4 * 2);                                  \
        *(uint2*)(sm + bo + off)         = make_uint2(h0, h1);                 \
        *(uint2*)(sm + bo + 16384 + off) = make_uint2(lo0, lo1);               \
    }                                                                          \
    {                                                                          \
        int row = t >> 3, c4 = (t & 7) * 4;                                    \
        uint32_t h0, lo0, h1, lo1;                                             \
        split2(sbv.x, sbv.y, h0, lo0);                                         \
        split2(sbv.z, sbv.w, h1, lo1);                                         \
        uint32_t off = SZ(row * 64 + c4 * 2);                                  \
        *(uint2*)(sm + bo + 32768 + off) = make_uint2(h0, h1);                 \
        *(uint2*)(sm + bo + 34816 + off) = make_uint2(lo0, lo1);               \
    } }

    F2_LOAD(0);
    F2_STORE(0);
    __syncthreads();
#pragma unroll 1
    for (int c = 0; c < 8; c++) {
        if (c + 1 < 8) F2_LOAD((c + 1) * 32);
        chunk_256x32(acc, sb + (c & 1) * F2_BUF, aoff, boff, 16384u, 2048u);
        if (c + 1 < 8) F2_STORE((c + 1) & 1);
        __syncthreads();
    }
    // epilogue: stage [32n][260] fp32, coalesced writes + bias, then LN2 stats
    __syncthreads();
    float* ep = (float*)sm;
#pragma unroll
    for (int mi = 0; mi < 2; mi++)
#pragma unroll
        for (int nj = 0; nj < 4; nj++) {
            int m = wid * 32 + mi * 16 + gid;
            int cN = nj * 8 + tig * 2;
            ep[cN * 260 + m]           = acc[mi][nj][0];
            ep[(cN + 1) * 260 + m]     = acc[mi][nj][1];
            ep[cN * 260 + m + 8]       = acc[mi][nj][2];
            ep[(cN + 1) * 260 + m + 8] = acc[mi][nj][3];
        }
    __syncthreads();
#pragma unroll
    for (int it = 0; it < 8; it++) {
        int idx = it * 256 + t;
        int nn = idx >> 6, c4 = (idx & 63) * 4;
        float4 v = *(float4*)&ep[nn * 260 + c4];
        float4 bv = *(const float4*)&b2[m0 + c4];
        v.x += bv.x; v.y += bv.y; v.z += bv.z; v.w += bv.w;
        *(float4*)&g_h2[(size_t)nn * DOUT + m0 + c4] = v;
    }
    // LN2 partial stats: 8 lanes per n
    {
        int nn = t >> 3, seg = t & 7;
        float s = 0.f, s2 = 0.f;
#pragma unroll
        for (int j = seg * 32; j < seg * 32 + 32; j++) {
            float v = ep[nn * 260 + j] + b2[m0 + j];
            s += v; s2 += v * v;
        }
#pragma unroll
        for (int o = 4; o; o >>= 1) {
            s  += __shfl_xor_sync(0xffffffffu, s, o);
            s2 += __shfl_xor_sync(0xffffffffu, s2, o);
        }
        if (seg == 0) {
            atomicAdd(&g_stats[nn * 2],     s);
            atomicAdd(&g_stats[nn * 2 + 1], s2);
        }
    }
}

// ====================== K7: out conv + LN2-on-load + BN + residual ============
#define GK_BUF 32768
#define GK_SMEM (2 * GK_BUF)
__global__ void __launch_bounds__(256) k_out_mma(const float* __restrict__ x,
                                                 const float* __restrict__ wout,
                                                 const float* __restrict__ g2,
                                                 const float* __restrict__ be2,
                                                 const float* __restrict__ bng,
                                                 const float* __restrict__ bnb,
                                                 const float* __restrict__ bnm,
                                                 const float* __restrict__ bnv,
                                                 float* __restrict__ out) {
    extern __shared__ char sm[];
    const int lt = blockIdx.x, ct = blockIdx.y, n = blockIdx.z;
    const int l0 = lt * 128, c0b = ct * 128;
    uint32_t sb = s2u(sm);
    int t = threadIdx.x, wid = t >> 5, lane = t & 31;
    int wm = wid >> 1, wn = wid & 1;
    int gid = lane >> 2, tig = lane & 3;

    float mu2 = g_stats[n * 2] * (1.f / DOUT);
    float rs2 = rsqrtf(g_stats[n * 2 + 1] * (1.f / DOUT) - mu2 * mu2 + EPSf);

    uint32_t aoff[2][2], boff[4][2];
    mk_aoff(aoff, wm * 32, lane, 0u);
    mk_boff<4>(boff, wn * 64, lane, 16384u);

    float acc[2][8][4];
#pragma unroll
    for (int i = 0; i < 2; i++)
#pragma unroll
        for (int j = 0; j < 8; j++)
#pragma unroll
            for (int q = 0; q < 4; q++) acc[i][j][q] = 0.f;

    const int la = t & 127, cg = t >> 7;
    const float* yc  = g_h2 + (size_t)n * DOUT + l0 + la;
    const float* g2c = g2  + l0 + la;
    const float* b2c = be2 + l0 + la;

    float4 sav[4];
    float sbr[4][4];

#define K7_LOAD(o0) {                                                          \
    _Pragma("unroll")                                                          \
    for (int it = 0; it < 4; it++) {                                           \
        int idx = it * 256 + t;                                                \
        int row = idx >> 3, c4 = (idx & 7) * 4;                                \
        sav[it] = *(const float4*)&wout[(size_t)(c0b + row) * ICc + (o0) + c4];\
    }                                                                          \
    _Pragma("unroll")                                                          \
    for (int it = 0; it < 4; it++) {                                           \
        int ck = (it * 2 + cg) * 4;                                            \
        _Pragma("unroll")                                                      \
        for (int j = 0; j < 4; j++) {                                          \
            size_t mo = (size_t)((o0) + ck + j) * Ll;                          \
            sbr[it][j] = (yc[mo] - mu2) * rs2 * g2c[mo] + b2c[mo];             \
        }                                                                      \
    } }
#define K7_STORE(bsel) {                                                       \
    uint32_t bo = (bsel) * GK_BUF;                                             \
    _Pragma("unroll")                                                          \
    for (int it = 0; it < 4; it++) {                                           \
        int idx = it * 256 + t;                                                \
        int row = idx >> 3, c4 = (idx & 7) * 4;                                \
        uint32_t h0, lo0, h1, lo1;                                             \
        split2(sav[it].x, sav[it].y, h0, lo0);                                 \
        split2(sav[it].z, sav[it].w, h1, lo1);                                 \
        uint32_t off = SZ(row * 64 + c4 * 2);                                  \
        *(uint2*)(sm + bo + off)        = make_uint2(h0, h1);                  \
        *(uint2*)(sm + bo + 8192 + off) = make_uint2(lo0, lo1);                \
    }                                                                          \
    _Pragma("unroll")                                                          \
    for (int it = 0; it < 4; it++) {                                           \
        int ck = (it * 2 + cg) * 4;                                            \
        uint32_t h0, lo0, h1, lo1;                                             \
        split2(sbr[it][0], sbr[it][1], h0, lo0);                               \
        split2(sbr[it][2], sbr[it][3], h1, lo1);                               \
        uint32_t off = SZ(la * 64 + ck * 2);                                   \
        *(uint2*)(sm + bo + 16384 + off) = make_uint2(h0, h1);                 \
        *(uint2*)(sm + bo + 24576 + off) = make_uint2(lo0, lo1);               \
    } }

    K7_LOAD(0);
    K7_STORE(0);
    __syncthreads();
#pragma unroll 1
    for (int c = 0; c < 4; c++) {
        if (c + 1 < 4) K7_LOAD((c + 1) * 32);
        chunk_128x128(acc, sb + (c & 1) * GK_BUF, aoff, boff, 8192u, 8192u);
        if (c + 1 < 4) K7_STORE((c + 1) & 1);
        __syncthreads();
    }
#pragma unroll
    for (int mi = 0; mi < 2; mi++)
#pragma unroll
        for (int r2 = 0; r2 < 2; r2++) {
            int c = c0b + wm * 32 + mi * 16 + gid + r2 * 8;
            float sc = bng[c] * rsqrtf(bnv[c] + EPSf);
            float mb = bnm[c], bb = bnb[c];
            size_t base = ((size_t)n * Cc + c) * Ll + l0 + wn * 64;
#pragma unroll
            for (int nj = 0; nj < 8; nj++) {
                int lo = nj * 8 + tig * 2;
                float2 xv = *(const float2*)&x[base + lo];
                float2 o;
                o.x = (acc[mi][nj][r2 * 2]     - mb) * sc + bb + xv.x;
                o.y = (acc[mi][nj][r2 * 2 + 1] - mb) * sc + bb + xv.y;
                *(float2*)&out[base + lo] = o;
            }
        }
}

// ---------------- launch -------------------------------------------------------
extern "C" void kernel_launch(void* const* d_in, const int* in_sizes, int n_in,
                              void* d_out, int out_size) {
    const float* x      = (const float*)d_in[0];
    const float* wq     = (const float*)d_in[1];
    const float* wk     = (const float*)d_in[2];
    const float* gamma1 = (const float*)d_in[3];
    const float* beta1  = (const float*)d_in[4];
    const float* w1     = (const float*)d_in[5];
    const float* b1     = (const float*)d_in[6];
    const float* w2     = (const float*)d_in[7];
    const float* b2     = (const float*)d_in[8];
    const float* gamma2 = (const float*)d_in[9];
    const float* beta2  = (const float*)d_in[10];
    const float* w_out  = (const float*)d_in[11];
    const float* bn_g   = (const float*)d_in[12];
    const float* bn_b   = (const float*)d_in[13];
    const float* bn_m   = (const float*)d_in[14];
    const float* bn_v   = (const float*)d_in[15];
    float* out = (float*)d_out;

    cudaFuncSetAttribute(k_qk_mma,   cudaFuncAttributeMaxDynamicSharedMemorySize, QK_SMEM);
    cudaFuncSetAttribute(k_ffn2_mma, cudaFuncAttributeMaxDynamicSharedMemorySize, F2_SMEM);
    cudaFuncSetAttribute(k_out_mma,  cudaFuncAttributeMaxDynamicSharedMemorySize, GK_SMEM);

    k_init<<<32, 256>>>(b1);
    k_qk_mma<<<dim3(16, 32), 256, QK_SMEM>>>(x, wq, wk);
    k_attn<<<4096, 256>>>();
    k_ln1<<<dim3(4, 32), 256>>>(gamma1, beta1);
    k_ffn1<<<dim3(16, 24), 256>>>(w1);
    k_ffn2_mma<<<512, 256, F2_SMEM>>>(w2, b2);
    k_out_mma<<<dim3(8, 2, 32), 256, GK_SMEM>>>(x, w_out, gamma2, beta2,
                                                bn_g, bn_b, bn_m, bn_v, out);
}

// round 5
// speedup vs baseline: 1.0391x; 1.0391x over previous
#include <cuda_runtime.h>
#include <cuda_bf16.h>
#include <cstdint>
#include <math.h>

#define Nn 32
#define Cc 256
#define ICc 128
#define Hh 32
#define Ww 32
#define Ll 1024
#define DA 9216
#define DOUT 131072
#define EPSf 1e-5f

// ---------------- scratch ----------------------------------------------------
__device__ float g_qt[Nn * Ll * ICc];     // q [n][l][o]; later reused as y_norm^T
__device__ float g_kt[Nn * Ll * ICc];     // k [n][l][o]
__device__ float g_f[Nn * DA];
__device__ float g_h1[Nn * Cc];
__device__ float g_h2[Nn * DOUT];         // [n][m]
__device__ float g_stats[Nn * 2];         // LN2 sums
__device__ float g_stats1[Nn * 2];        // LN1 sums

// ---------------- mma.sync helpers -------------------------------------------
__device__ __forceinline__ uint32_t s2u(const void* p) {
    uint32_t a;
    asm("{ .reg .u64 t; cvta.to.shared.u64 t, %1; cvt.u32.u64 %0, t; }" : "=r"(a) : "l"(p));
    return a;
}
#define SZ(o) ((uint32_t)(o) ^ ((((uint32_t)(o)) >> 3) & 0x30))

__device__ __forceinline__ void ldsm4(uint32_t* r, uint32_t a) {
    asm volatile("ldmatrix.sync.aligned.m8n8.x4.shared.b16 {%0,%1,%2,%3}, [%4];"
                 : "=r"(r[0]), "=r"(r[1]), "=r"(r[2]), "=r"(r[3]) : "r"(a));
}
__device__ __forceinline__ void mma16816(float* d, const uint32_t* a, uint32_t b0, uint32_t b1) {
    asm volatile(
        "mma.sync.aligned.m16n8k16.row.col.f32.bf16.bf16.f32 "
        "{%0,%1,%2,%3}, {%4,%5,%6,%7}, {%8,%9}, {%0,%1,%2,%3};"
        : "+f"(d[0]), "+f"(d[1]), "+f"(d[2]), "+f"(d[3])
        : "r"(a[0]), "r"(a[1]), "r"(a[2]), "r"(a[3]), "r"(b0), "r"(b1));
}

__device__ __forceinline__ uint32_t bf2u(__nv_bfloat16 a, __nv_bfloat16 b) {
    return (uint32_t)__bfloat16_as_ushort(a) | ((uint32_t)__bfloat16_as_ushort(b) << 16);
}
__device__ __forceinline__ void split2(float a, float b, uint32_t& hi, uint32_t& lo) {
    __nv_bfloat16 ha = __float2bfloat16(a), hb = __float2bfloat16(b);
    __nv_bfloat16 la = __float2bfloat16(a - __bfloat162float(ha));
    __nv_bfloat16 lb = __float2bfloat16(b - __bfloat162float(hb));
    hi = bf2u(ha, hb);
    lo = bf2u(la, lb);
}

// 3-pass hi/lo MMA over one K=32 chunk; warp tile 32x64.
__device__ __forceinline__ void chunk_128x128(float (&acc)[2][8][4], uint32_t base,
                                              const uint32_t (&aoff)[2][2],
                                              const uint32_t (&boff)[4][2],
                                              uint32_t aLo, uint32_t bLo) {
#pragma unroll
    for (int ks = 0; ks < 2; ks++) {
        uint32_t ah0[4], ah1[4], al0[4], al1[4];
        ldsm4(ah0, base + aoff[0][ks]);
        ldsm4(ah1, base + aoff[1][ks]);
        ldsm4(al0, base + aoff[0][ks] + aLo);
        ldsm4(al1, base + aoff[1][ks] + aLo);
#pragma unroll
        for (int p = 0; p < 4; p++) {
            uint32_t bh[4], bl[4];
            ldsm4(bh, base + boff[p][ks]);
            ldsm4(bl, base + boff[p][ks] + bLo);
            mma16816(acc[0][2 * p],     ah0, bh[0], bh[1]);
            mma16816(acc[0][2 * p + 1], ah0, bh[2], bh[3]);
            mma16816(acc[1][2 * p],     ah1, bh[0], bh[1]);
            mma16816(acc[1][2 * p + 1], ah1, bh[2], bh[3]);
            mma16816(acc[0][2 * p],     ah0, bl[0], bl[1]);
            mma16816(acc[0][2 * p + 1], ah0, bl[2], bl[3]);
            mma16816(acc[1][2 * p],     ah1, bl[0], bl[1]);
            mma16816(acc[1][2 * p + 1], ah1, bl[2], bl[3]);
            mma16816(acc[0][2 * p],     al0, bh[0], bh[1]);
            mma16816(acc[0][2 * p + 1], al0, bh[2], bh[3]);
            mma16816(acc[1][2 * p],     al1, bh[0], bh[1]);
            mma16816(acc[1][2 * p + 1], al1, bh[2], bh[3]);
        }
    }
}
// block tile 256x32, warp tile 32x32
__device__ __forceinline__ void chunk_256x32(float (&acc)[2][4][4], uint32_t base,
                                             const uint32_t (&aoff)[2][2],
                                             const uint32_t (&boff)[2][2],
                                             uint32_t aLo, uint32_t bLo) {
#pragma unroll
    for (int ks = 0; ks < 2; ks++) {
        uint32_t ah0[4], ah1[4], al0[4], al1[4];
        ldsm4(ah0, base + aoff[0][ks]);
        ldsm4(ah1, base + aoff[1][ks]);
        ldsm4(al0, base + aoff[0][ks] + aLo);
        ldsm4(al1, base + aoff[1][ks] + aLo);
#pragma unroll
        for (int p = 0; p < 2; p++) {
            uint32_t bh[4], bl[4];
            ldsm4(bh, base + boff[p][ks]);
            ldsm4(bl, base + boff[p][ks] + bLo);
            mma16816(acc[0][2 * p],     ah0, bh[0], bh[1]);
            mma16816(acc[0][2 * p + 1], ah0, bh[2], bh[3]);
            mma16816(acc[1][2 * p],     ah1, bh[0], bh[1]);
            mma16816(acc[1][2 * p + 1], ah1, bh[2], bh[3]);
            mma16816(acc[0][2 * p],     ah0, bl[0], bl[1]);
            mma16816(acc[0][2 * p + 1], ah0, bl[2], bl[3]);
            mma16816(acc[1][2 * p],     ah1, bl[0], bl[1]);
            mma16816(acc[1][2 * p + 1], ah1, bl[2], bl[3]);
            mma16816(acc[0][2 * p],     al0, bh[0], bh[1]);
            mma16816(acc[0][2 * p + 1], al0, bh[2], bh[3]);
            mma16816(acc[1][2 * p],     al1, bh[0], bh[1]);
            mma16816(acc[1][2 * p + 1], al1, bh[2], bh[3]);
        }
    }
}

__device__ __forceinline__ void mk_aoff(uint32_t (&aoff)[2][2], int m_off, int lane,
                                        uint32_t planeA) {
    int sub = lane >> 3, rr = lane & 7;
#pragma unroll
    for (int mi = 0; mi < 2; mi++)
#pragma unroll
        for (int ks = 0; ks < 2; ks++) {
            int row = m_off + mi * 16 + (sub & 1) * 8 + rr;
            int byte = ks * 32 + (sub >> 1) * 16;
            aoff[mi][ks] = planeA + SZ(row * 64 + byte);
        }
}
template <int NP>
__device__ __forceinline__ void mk_boff(uint32_t (&boff)[NP][2], int n_off, int lane,
                                        uint32_t planeB) {
    int sub = lane >> 3, rr = lane & 7;
#pragma unroll
    for (int p = 0; p < NP; p++)
#pragma unroll
        for (int ks = 0; ks < 2; ks++) {
            int row = n_off + p * 16 + (sub >> 1) * 8 + rr;
            int byte = ks * 32 + (sub & 1) * 16;
            boff[p][ks] = planeB + SZ(row * 64 + byte);
        }
}

// ====================== K1: q/k conv (R3 unfused version) ====================
#define GK_BUF 32768
#define GK_SMEM (2 * GK_BUF)
__global__ void __launch_bounds__(256) k_qk_mma(const float* __restrict__ x,
                                                const float* __restrict__ wq,
                                                const float* __restrict__ wk) {
    extern __shared__ char sm[];
    const int lt = blockIdx.x, qk = blockIdx.y, n = blockIdx.z;
    const float* w = qk ? wk : wq;
    float* outp = qk ? g_kt : g_qt;
    const int l0 = lt * 128;
    uint32_t sb = s2u(sm);
    int t = threadIdx.x, wid = t >> 5, lane = t & 31;
    int wm = wid >> 1, wn = wid & 1;
    int gid = lane >> 2, tig = lane & 3;

    uint32_t aoff[2][2], boff[4][2];
    mk_aoff(aoff, wm * 32, lane, 0u);
    mk_boff<4>(boff, wn * 64, lane, 16384u);

    float acc[2][8][4];
#pragma unroll
    for (int i = 0; i < 2; i++)
#pragma unroll
        for (int j = 0; j < 8; j++)
#pragma unroll
            for (int q = 0; q < 4; q++) acc[i][j][q] = 0.f;

    const int la = t & 127, cg = t >> 7;
    const float* xc = x + (size_t)n * Cc * Ll + l0 + la;

    float sa[4][4];
    float4 sbv[4];

#define K1_LOAD(c0) {                                                          \
    _Pragma("unroll")                                                          \
    for (int it = 0; it < 4; it++) {                                           \
        int ck = (it * 2 + cg) * 4;                                            \
        sa[it][0] = xc[(size_t)((c0) + ck + 0) * Ll];                          \
        sa[it][1] = xc[(size_t)((c0) + ck + 1) * Ll];                          \
        sa[it][2] = xc[(size_t)((c0) + ck + 2) * Ll];                          \
        sa[it][3] = xc[(size_t)((c0) + ck + 3) * Ll];                          \
    }                                                                          \
    _Pragma("unroll")                                                          \
    for (int it = 0; it < 4; it++) {                                           \
        int idx = it * 256 + t;                                                \
        int row = idx >> 3, c4 = (idx & 7) * 4;                                \
        sbv[it] = *(const float4*)&w[(size_t)row * Cc + (c0) + c4];            \
    } }
#define K1_STORE(bsel) {                                                       \
    uint32_t bo = (bsel) * GK_BUF;                                             \
    _Pragma("unroll")                                                          \
    for (int it = 0; it < 4; it++) {                                           \
        int ck = (it * 2 + cg) * 4;                                            \
        uint32_t h0, lo0, h1, lo1;                                             \
        split2(sa[it][0], sa[it][1], h0, lo0);                                 \
        split2(sa[it][2], sa[it][3], h1, lo1);                                 \
        uint32_t off = SZ(la * 64 + ck * 2);                                   \
        *(uint2*)(sm + bo + off)        = make_uint2(h0, h1);                  \
        *(uint2*)(sm + bo + 8192 + off) = make_uint2(lo0, lo1);                \
    }                                                                          \
    _Pragma("unroll")                                                          \
    for (int it = 0; it < 4; it++) {                                           \
        int idx = it * 256 + t;                                                \
        int row = idx >> 3, c4 = (idx & 7) * 4;                                \
        uint32_t h0, lo0, h1, lo1;                                             \
        split2(sbv[it].x, sbv[it].y, h0, lo0);                                 \
        split2(sbv[it].z, sbv[it].w, h1, lo1);                                 \
        uint32_t off = SZ(row * 64 + c4 * 2);                                  \
        *(uint2*)(sm + bo + 16384 + off) = make_uint2(h0, h1);                 \
        *(uint2*)(sm + bo + 24576 + off) = make_uint2(lo0, lo1);               \
    } }

    K1_LOAD(0);
    K1_STORE(0);
    __syncthreads();
#pragma unroll 1
    for (int c = 0; c < 8; c++) {
        if (c + 1 < 8) K1_LOAD((c + 1) * 32);
        chunk_128x128(acc, sb + (c & 1) * GK_BUF, aoff, boff, 8192u, 8192u);
        if (c + 1 < 8) K1_STORE((c + 1) & 1);
        __syncthreads();
    }
#pragma unroll
    for (int mi = 0; mi < 2; mi++)
#pragma unroll
        for (int r2 = 0; r2 < 2; r2++) {
            int l = l0 + wm * 32 + mi * 16 + gid + r2 * 8;
            float* op = outp + ((size_t)(n << 10) + l) * ICc + wn * 64;
#pragma unroll
            for (int nj = 0; nj < 8; nj++)
                *(float2*)&op[nj * 8 + tig * 2] =
                    make_float2(acc[mi][nj][r2 * 2], acc[mi][nj][r2 * 2 + 1]);
        }
}

// ====================== K2: local attention + LN1 stats ======================
__global__ void __launch_bounds__(256) k_attn() {
    int wid = threadIdx.x >> 5;
    int gw = blockIdx.x * 8 + wid;
    int lane = threadIdx.x & 31;
    int n = gw >> 10;
    int l = gw & 1023;
    int h = l >> 5, w = l & 31;
    const float* qp = g_qt + ((size_t)(n << 10) + l) * ICc;
    float4 qv = *(const float4*)&qp[lane * 4];
    float acc[9];
#pragma unroll
    for (int r = 0; r < 9; r++) {
        int hh = h + r / 3 - 1;
        int ww = w + r % 3 - 1;
        float s = 0.f;
        if (hh >= 0 && hh < Hh && ww >= 0 && ww < Ww) {
            const float* kp = g_kt + ((size_t)(n << 10) + (hh << 5) + ww) * ICc;
            float4 kv = *(const float4*)&kp[lane * 4];
            s = qv.x * kv.x + qv.y * kv.y + qv.z * kv.z + qv.w * kv.w;
        }
#pragma unroll
        for (int off = 16; off; off >>= 1) s += __shfl_xor_sync(0xffffffffu, s, off);
        acc[r] = s;
    }
    float val = 0.f;
#pragma unroll
    for (int r = 0; r < 9; r++)
        if (lane == r) val = acc[r];
    if (lane < 9) g_f[(size_t)n * DA + lane * Ll + l] = 2.f * val;

    __shared__ float bs[16];
    if (lane == 0) {
        float s = 0.f, s2 = 0.f;
#pragma unroll
        for (int r = 0; r < 9; r++) {
            float v = 2.f * acc[r];
            s += v; s2 += v * v;
        }
        bs[wid] = s;
        bs[8 + wid] = s2;
    }
    __syncthreads();
    if (threadIdx.x == 0) {
        float S = 0.f, S2 = 0.f;
#pragma unroll
        for (int i = 0; i < 8; i++) { S += bs[i]; S2 += bs[8 + i]; }
        atomicAdd(&g_stats1[n * 2],     S);
        atomicAdd(&g_stats1[n * 2 + 1], S2);
    }
}

// ---------------- init --------------------------------------------------------
__global__ void k_init(const float* __restrict__ b1) {
    int t = blockIdx.x * blockDim.x + threadIdx.x;
    if (t < Nn * Cc) g_h1[t] = b1[t & 255];
    if (t < Nn * 2) { g_stats[t] = 0.f; g_stats1[t] = 0.f; }
}

// ---------------- LN1: normalize only -----------------------------------------
__global__ void __launch_bounds__(256) k_ln1(const float* __restrict__ g1,
                                             const float* __restrict__ be1) {
    int sl = blockIdx.x, n = blockIdx.y, t = threadIdx.x;
    float mu = g_stats1[n * 2] * (1.f / DA);
    float rs = rsqrtf(g_stats1[n * 2 + 1] * (1.f / DA) - mu * mu + EPSf);
    float4* fp4 = (float4*)(g_f + (size_t)n * DA);
    const float4* g4 = (const float4*)g1;
    const float4* b4 = (const float4*)be1;
    int base = sl * 576;
    for (int j = base + t; j < base + 576; j += 256) {
        float4 v = fp4[j];
        float4 gg = g4[j], bb = b4[j];
        v.x = (v.x - mu) * rs * gg.x + bb.x;
        v.y = (v.y - mu) * rs * gg.y + bb.y;
        v.z = (v.z - mu) * rs * gg.z + bb.z;
        v.w = (v.w - mu) * rs * gg.w + bb.w;
        fp4[j] = v;
    }
}

// ---------------- FFN1 split-K ------------------------------------------------
__global__ void __launch_bounds__(256) k_ffn1(const float* __restrict__ w1) {
    int c0 = blockIdx.x * 16;
    int jbase = blockIdx.y * 384;
    __shared__ float fs[32][33];
    __shared__ float ws[16][33];
    int t = threadIdx.x;
    int n = t & 31, cg = t >> 5;
    int c = c0 + cg * 2;
    float acc0 = 0.f, acc1 = 0.f;
    for (int jc = 0; jc < 12; jc++) {
        int j0 = jbase + jc * 32;
        {
            int nn = t >> 3, jj = (t & 7) * 4;
            float4 v = *(const float4*)&g_f[(size_t)nn * DA + j0 + jj];
            fs[nn][jj] = v.x; fs[nn][jj + 1] = v.y; fs[nn][jj + 2] = v.z; fs[nn][jj + 3] = v.w;
        }
        for (int idx = t; idx < 512; idx += 256) {
            int cl = idx >> 5, jj = idx & 31;
            ws[cl][jj] = w1[(size_t)(c0 + cl) * DA + j0 + jj];
        }
        __syncthreads();
#pragma unroll
        for (int jj = 0; jj < 32; jj++) {
            float fv = fs[n][jj];
            acc0 += fv * ws[cg * 2][jj];
            acc1 += fv * ws[cg * 2 + 1][jj];
        }
        __syncthreads();
    }
    atomicAdd(&g_h1[n * Cc + c],     acc0);
    atomicAdd(&g_h1[n * Cc + c + 1], acc1);
}

// ====================== K5: FFN2 + LN2 stats ==================================
#define F2_BUF 36864
#define F2_SMEM (2 * F2_BUF)
__global__ void __launch_bounds__(256) k_ffn2_mma(const float* __restrict__ w2,
                                                  const float* __restrict__ b2) {
    extern __shared__ char sm[];
    const int m0 = blockIdx.x * 256;
    uint32_t sb = s2u(sm);
    int t = threadIdx.x, wid = t >> 5, lane = t & 31;
    int gid = lane >> 2, tig = lane & 3;

    uint32_t aoff[2][2], boff[2][2];
    mk_aoff(aoff, wid * 32, lane, 0u);
    mk_boff<2>(boff, 0, lane, 32768u);

    float acc[2][4][4];
#pragma unroll
    for (int i = 0; i < 2; i++)
#pragma unroll
        for (int j = 0; j < 4; j++)
#pragma unroll
            for (int q = 0; q < 4; q++) acc[i][j][q] = 0.f;

    float4 sav[8];
    float4 sbv;

#define F2_LOAD(c0) {                                                          \
    _Pragma("unroll")                                                          \
    for (int it = 0; it < 8; it++) {                                           \
        int idx = it * 256 + t;                                                \
        int row = idx >> 3, c4 = (idx & 7) * 4;                                \
        sav[it] = *(const float4*)&w2[(size_t)(m0 + row) * Cc + (c0) + c4];    \
    }                                                                          \
    {                                                                          \
        int row = t >> 3, c4 = (t & 7) * 4;                                    \
        float4 v = *(const float4*)&g_h1[(size_t)row * Cc + (c0) + c4];        \
        v.x = fmaxf(v.x, 0.f); v.y = fmaxf(v.y, 0.f);                          \
        v.z = fmaxf(v.z, 0.f); v.w = fmaxf(v.w, 0.f);                          \
        sbv = v;                                                               \
    } }
#define F2_STORE(bsel) {                                                       \
    uint32_t bo = (bsel) * F2_BUF;                                             \
    _Pragma("unroll")                                                          \
    for (int it = 0; it < 8; it++) {                                           \
        int idx = it * 256 + t;                                                \
        int row = idx >> 3, c4 = (idx & 7) * 4;                                \
        uint32_t h0, lo0, h1, lo1;                                             \
        split2(sav[it].x, sav[it].y, h0, lo0);                                 \
        split2(sav[it].z, sav[it].w, h1, lo1);                                 \
        uint32_t off = SZ(row * 64 + c4 * 2);                                  \
        *(uint2*)(sm + bo + off)         = make_uint2(h0, h1);                 \
        *(uint2*)(sm + bo + 16384 + off) = make_uint2(lo0, lo1);               \
    }                                                                          \
    {                                                                          \
        int row = t >> 3, c4 = (t & 7) * 4;                                    \
        uint32_t h0, lo0, h1, lo1;                                             \
        split2(sbv.x, sbv.y, h0, lo0);                                         \
        split2(sbv.z, sbv.w, h1, lo1);                                         \
        uint32_t off = SZ(row * 64 + c4 * 2);                                  \
        *(uint2*)(sm + bo + 32768 + off) = make_uint2(h0, h1);                 \
        *(uint2*)(sm + bo + 34816 + off) = make_uint2(lo0, lo1);               \
    } }

    F2_LOAD(0);
    F2_STORE(0);
    __syncthreads();
#pragma unroll 1
    for (int c = 0; c < 8; c++) {
        if (c + 1 < 8) F2_LOAD((c + 1) * 32);
        chunk_256x32(acc, sb + (c & 1) * F2_BUF, aoff, boff, 16384u, 2048u);
        if (c + 1 < 8) F2_STORE((c + 1) & 1);
        __syncthreads();
    }
    __syncthreads();
    float* ep = (float*)sm;
#pragma unroll
    for (int mi = 0; mi < 2; mi++)
#pragma unroll
        for (int nj = 0; nj < 4; nj++) {
            int m = wid * 32 + mi * 16 + gid;
            int cN = nj * 8 + tig * 2;
            ep[cN * 260 + m]           = acc[mi][nj][0];
            ep[(cN + 1) * 260 + m]     = acc[mi][nj][1];
            ep[cN * 260 + m + 8]       = acc[mi][nj][2];
            ep[(cN + 1) * 260 + m + 8] = acc[mi][nj][3];
        }
    __syncthreads();
#pragma unroll
    for (int it = 0; it < 8; it++) {
        int idx = it * 256 + t;
        int nn = idx >> 6, c4 = (idx & 63) * 4;
        float4 v = *(float4*)&ep[nn * 260 + c4];
        float4 bv = *(const float4*)&b2[m0 + c4];
        v.x += bv.x; v.y += bv.y; v.z += bv.z; v.w += bv.w;
        *(float4*)&g_h2[(size_t)nn * DOUT + m0 + c4] = v;
    }
    // LN2 partial stats: 8 lanes per n
    {
        int nn = t >> 3, seg = t & 7;
        float s = 0.f, s2 = 0.f;
#pragma unroll
        for (int j = seg * 32; j < seg * 32 + 32; j++) {
            float v = ep[nn * 260 + j] + b2[m0 + j];
            s += v; s2 += v * v;
        }
#pragma unroll
        for (int o = 4; o; o >>= 1) {
            s  += __shfl_xor_sync(0xffffffffu, s, o);
            s2 += __shfl_xor_sync(0xffffffffu, s2, o);
        }
        if (seg == 0) {
            atomicAdd(&g_stats[nn * 2],     s);
            atomicAdd(&g_stats[nn * 2 + 1], s2);
        }
    }
}

// ====================== K6: LN2 normalize + transpose into g_qt ===============
// in:  g_h2[n][o*Ll + l]   out: g_qt[n][l*ICc + o]  (y_norm^T)
// block: 64(l) x 64(o) tile via smem; grid (16 ltiles, 2 otiles, 32 n)
__global__ void __launch_bounds__(256) k_ln2t(const float* __restrict__ g2,
                                              const float* __restrict__ be2) {
    __shared__ float ts[64][65];
    int lt = blockIdx.x, ot = blockIdx.y, n = blockIdx.z;
    int l0 = lt * 64, o0 = ot * 64;
    int t = threadIdx.x;
    float mu = g_stats[n * 2] * (1.f / DOUT);
    float rs = rsqrtf(g_stats[n * 2 + 1] * (1.f / DOUT) - mu * mu + EPSf);
    // load: 64 o-rows x 64 l-cols, coalesced along l (4 floats/thread via float4? l strided by t&15*4)
    int li = (t & 15) * 4, oi = t >> 4;   // 16 o rows per pass, 4 passes
#pragma unroll
    for (int p = 0; p < 4; p++) {
        int o = oi + p * 16;
        size_t m = (size_t)(o0 + o) * Ll + l0 + li;
        float4 v = *(const float4*)&g_h2[(size_t)n * DOUT + m];
        float4 gg = *(const float4*)&g2[m];
        float4 bb = *(const float4*)&be2[m];
        ts[li + 0][o] = (v.x - mu) * rs * gg.x + bb.x;
        ts[li + 1][o] = (v.y - mu) * rs * gg.y + bb.y;
        ts[li + 2][o] = (v.z - mu) * rs * gg.z + bb.z;
        ts[li + 3][o] = (v.w - mu) * rs * gg.w + bb.w;
    }
    __syncthreads();
    // store: 64 l-rows x 64 o-cols, coalesced along o
    int oj = (t & 15) * 4, lj = t >> 4;
#pragma unroll
    for (int p = 0; p < 4; p++) {
        int l = lj + p * 16;
        float4 v = make_float4(ts[l][oj], ts[l][oj + 1], ts[l][oj + 2], ts[l][oj + 3]);
        *(float4*)&g_qt[((size_t)(n << 10) + l0 + l) * ICc + o0 + oj] = v;
    }
}

// ====================== K7: out conv + BN + residual ==========================
// D[c][l] = sum_o wout[c][o] * yt[l][o]; both operands K-major coalesced.
__global__ void __launch_bounds__(256) k_out_mma(const float* __restrict__ x,
                                                 const float* __restrict__ wout,
                                                 const float* __restrict__ bng,
                                                 const float* __restrict__ bnb,
                                                 const float* __restrict__ bnm,
                                                 const float* __restrict__ bnv,
                                                 float* __restrict__ out) {
    extern __shared__ char sm[];
    const int lt = blockIdx.x, ct = blockIdx.y, n = blockIdx.z;
    const int l0 = lt * 128, c0b = ct * 128;
    uint32_t sb = s2u(sm);
    int t = threadIdx.x, wid = t >> 5, lane = t & 31;
    int wm = wid >> 1, wn = wid & 1;
    int gid = lane >> 2, tig = lane & 3;

    uint32_t aoff[2][2], boff[4][2];
    mk_aoff(aoff, wm * 32, lane, 0u);
    mk_boff<4>(boff, wn * 64, lane, 16384u);

    float acc[2][8][4];
#pragma unroll
    for (int i = 0; i < 2; i++)
#pragma unroll
        for (int j = 0; j < 8; j++)
#pragma unroll
            for (int q = 0; q < 4; q++) acc[i][j][q] = 0.f;

    const float* ytp = g_qt + ((size_t)(n << 10) + l0) * ICc;

    float4 sav[4], sbw[4];

#define K7_LOAD(o0) {                                                          \
    _Pragma("unroll")                                                          \
    for (int it = 0; it < 4; it++) {                                           \
        int idx = it * 256 + t;                                                \
        int row = idx >> 3, c4 = (idx & 7) * 4;                                \
        sav[it] = *(const float4*)&wout[(size_t)(c0b + row) * ICc + (o0) + c4];\
        sbw[it] = *(const float4*)&ytp[(size_t)row * ICc + (o0) + c4];         \
    } }
#define K7_STORE(bsel) {                                                       \
    uint32_t bo = (bsel) * GK_BUF;                                             \
    _Pragma("unroll")                                                          \
    for (int it = 0; it < 4; it++) {                                           \
        int idx = it * 256 + t;                                                \
        int row = idx >> 3, c4 = (idx & 7) * 4;                                \
        uint32_t off = SZ(row * 64 + c4 * 2);                                  \
        uint32_t h0, lo0, h1, lo1;                                             \
        split2(sav[it].x, sav[it].y, h0, lo0);                                 \
        split2(sav[it].z, sav[it].w, h1, lo1);                                 \
        *(uint2*)(sm + bo + off)        = make_uint2(h0, h1);                  \
        *(uint2*)(sm + bo + 8192 + off) = make_uint2(lo0, lo1);                \
        split2(sbw[it].x, sbw[it].y, h0, lo0);                                 \
        split2(sbw[it].z, sbw[it].w, h1, lo1);                                 \
        *(uint2*)(sm + bo + 16384 + off) = make_uint2(h0, h1);                 \
        *(uint2*)(sm + bo + 24576 + off) = make_uint2(lo0, lo1);               \
    } }

    K7_LOAD(0);
    K7_STORE(0);
    __syncthreads();
#pragma unroll 1
    for (int c = 0; c < 4; c++) {
        if (c + 1 < 4) K7_LOAD((c + 1) * 32);
        chunk_128x128(acc, sb + (c & 1) * GK_BUF, aoff, boff, 8192u, 8192u);
        if (c + 1 < 4) K7_STORE((c + 1) & 1);
        __syncthreads();
    }
#pragma unroll
    for (int mi = 0; mi < 2; mi++)
#pragma unroll
        for (int r2 = 0; r2 < 2; r2++) {
            int c = c0b + wm * 32 + mi * 16 + gid + r2 * 8;
            float sc = bng[c] * rsqrtf(bnv[c] + EPSf);
            float mb = bnm[c], bb = bnb[c];
            size_t base = ((size_t)n * Cc + c) * Ll + l0 + wn * 64;
#pragma unroll
            for (int nj = 0; nj < 8; nj++) {
                int lo = nj * 8 + tig * 2;
                float2 xv = *(const float2*)&x[base + lo];
                float2 o;
                o.x = (acc[mi][nj][r2 * 2]     - mb) * sc + bb + xv.x;
                o.y = (acc[mi][nj][r2 * 2 + 1] - mb) * sc + bb + xv.y;
                *(float2*)&out[base + lo] = o;
            }
        }
}

// ---------------- launch -------------------------------------------------------
extern "C" void kernel_launch(void* const* d_in, const int* in_sizes, int n_in,
                              void* d_out, int out_size) {
    const float* x      = (const float*)d_in[0];
    const float* wq     = (const float*)d_in[1];
    const float* wk     = (const float*)d_in[2];
    const float* gamma1 = (const float*)d_in[3];
    const float* beta1  = (const float*)d_in[4];
    const float* w1     = (const float*)d_in[5];
    const float* b1     = (const float*)d_in[6];
    const float* w2     = (const float*)d_in[7];
    const float* b2     = (const float*)d_in[8];
    const float* gamma2 = (const float*)d_in[9];
    const float* beta2  = (const float*)d_in[10];
    const float* w_out  = (const float*)d_in[11];
    const float* bn_g   = (const float*)d_in[12];
    const float* bn_b   = (const float*)d_in[13];
    const float* bn_m   = (const float*)d_in[14];
    const float* bn_v   = (const float*)d_in[15];
    float* out = (float*)d_out;

    cudaFuncSetAttribute(k_qk_mma,   cudaFuncAttributeMaxDynamicSharedMemorySize, GK_SMEM);
    cudaFuncSetAttribute(k_ffn2_mma, cudaFuncAttributeMaxDynamicSharedMemorySize, F2_SMEM);
    cudaFuncSetAttribute(k_out_mma,  cudaFuncAttributeMaxDynamicSharedMemorySize, GK_SMEM);

    k_init<<<32, 256>>>(b1);
    k_qk_mma<<<dim3(8, 2, 32), 256, GK_SMEM>>>(x, wq, wk);
    k_attn<<<4096, 256>>>();
    k_ln1<<<dim3(4, 32), 256>>>(gamma1, beta1);
    k_ffn1<<<dim3(16, 24), 256>>>(w1);
    k_ffn2_mma<<<512, 256, F2_SMEM>>>(w2, b2);
    k_ln2t<<<dim3(16, 2, 32), 256>>>(gamma2, beta2);
    k_out_mma<<<dim3(8, 2, 32), 256, GK_SMEM>>>(x, w_out, bn_g, bn_b, bn_m, bn_v, out);
}

// round 6
// speedup vs baseline: 1.1545x; 1.1111x over previous
#include <cuda_runtime.h>
#include <cuda_bf16.h>
#include <cstdint>
#include <math.h>

#define Nn 32
#define Cc 256
#define ICc 128
#define Hh 32
#define Ww 32
#define Ll 1024
#define DA 9216
#define DOUT 131072
#define EPSf 1e-5f

// ---------------- scratch ----------------------------------------------------
__device__ float g_qt[Nn * Ll * ICc];     // q [n][l][o]; later reused as y_norm^T
__device__ float g_kt[Nn * Ll * ICc];     // k [n][l][o]
__device__ float g_f[Nn * DA];
__device__ float g_h1[Nn * Cc];
__device__ float g_h2[Nn * DOUT];         // [n][m]
__device__ float g_stats[Nn * 2];         // LN2 sums
__device__ float g_stats1[Nn * 2];        // LN1 sums

// ---------------- mma.sync helpers -------------------------------------------
__device__ __forceinline__ uint32_t s2u(const void* p) {
    uint32_t a;
    asm("{ .reg .u64 t; cvta.to.shared.u64 t, %1; cvt.u32.u64 %0, t; }" : "=r"(a) : "l"(p));
    return a;
}
#define SZ(o) ((uint32_t)(o) ^ ((((uint32_t)(o)) >> 3) & 0x30))

__device__ __forceinline__ void ldsm4(uint32_t* r, uint32_t a) {
    asm volatile("ldmatrix.sync.aligned.m8n8.x4.shared.b16 {%0,%1,%2,%3}, [%4];"
                 : "=r"(r[0]), "=r"(r[1]), "=r"(r[2]), "=r"(r[3]) : "r"(a));
}
__device__ __forceinline__ void mma16816(float* d, const uint32_t* a, uint32_t b0, uint32_t b1) {
    asm volatile(
        "mma.sync.aligned.m16n8k16.row.col.f32.bf16.bf16.f32 "
        "{%0,%1,%2,%3}, {%4,%5,%6,%7}, {%8,%9}, {%0,%1,%2,%3};"
        : "+f"(d[0]), "+f"(d[1]), "+f"(d[2]), "+f"(d[3])
        : "r"(a[0]), "r"(a[1]), "r"(a[2]), "r"(a[3]), "r"(b0), "r"(b1));
}

// packed split: hi = bf16x2(a,b) [a in low half], lo = bf16x2 of residuals
__device__ __forceinline__ void split2(float a, float b, uint32_t& hi, uint32_t& lo) {
    uint32_t h;
    asm("cvt.rn.bf16x2.f32 %0, %1, %2;" : "=r"(h) : "f"(b), "f"(a));
    float fa = __uint_as_float(h << 16);
    float fb = __uint_as_float(h & 0xffff0000u);
    float la = a - fa, lb = b - fb;
    asm("cvt.rn.bf16x2.f32 %0, %1, %2;" : "=r"(lo) : "f"(lb), "f"(la));
    hi = h;
}

// ---- pass-major chunk: preload B frags; RAW distance = 16 MMAs --------------
__device__ __forceinline__ void chunk_128x128(float (&acc)[2][8][4], uint32_t base,
                                              const uint32_t (&aoff)[2][2],
                                              const uint32_t (&boff)[4][2],
                                              uint32_t aLo, uint32_t bLo) {
#pragma unroll
    for (int ks = 0; ks < 2; ks++) {
        uint32_t ah[2][4], al[2][4], b[4][4];
        ldsm4(ah[0], base + aoff[0][ks]);
        ldsm4(ah[1], base + aoff[1][ks]);
#pragma unroll
        for (int p = 0; p < 4; p++) ldsm4(b[p], base + boff[p][ks]);
        // pass 1: Ah x Bh
#pragma unroll
        for (int p = 0; p < 4; p++) {
            mma16816(acc[0][2 * p],     ah[0], b[p][0], b[p][1]);
            mma16816(acc[0][2 * p + 1], ah[0], b[p][2], b[p][3]);
            mma16816(acc[1][2 * p],     ah[1], b[p][0], b[p][1]);
            mma16816(acc[1][2 * p + 1], ah[1], b[p][2], b[p][3]);
        }
        ldsm4(al[0], base + aoff[0][ks] + aLo);
        ldsm4(al[1], base + aoff[1][ks] + aLo);
        // pass 2: Al x Bh
#pragma unroll
        for (int p = 0; p < 4; p++) {
            mma16816(acc[0][2 * p],     al[0], b[p][0], b[p][1]);
            mma16816(acc[0][2 * p + 1], al[0], b[p][2], b[p][3]);
            mma16816(acc[1][2 * p],     al[1], b[p][0], b[p][1]);
            mma16816(acc[1][2 * p + 1], al[1], b[p][2], b[p][3]);
        }
#pragma unroll
        for (int p = 0; p < 4; p++) ldsm4(b[p], base + boff[p][ks] + bLo);
        // pass 3: Ah x Bl
#pragma unroll
        for (int p = 0; p < 4; p++) {
            mma16816(acc[0][2 * p],     ah[0], b[p][0], b[p][1]);
            mma16816(acc[0][2 * p + 1], ah[0], b[p][2], b[p][3]);
            mma16816(acc[1][2 * p],     ah[1], b[p][0], b[p][1]);
            mma16816(acc[1][2 * p + 1], ah[1], b[p][2], b[p][3]);
        }
    }
}
// block tile 256x32, warp tile 32x32, pass-major
__device__ __forceinline__ void chunk_256x32(float (&acc)[2][4][4], uint32_t base,
                                             const uint32_t (&aoff)[2][2],
                                             const uint32_t (&boff)[2][2],
                                             uint32_t aLo, uint32_t bLo) {
#pragma unroll
    for (int ks = 0; ks < 2; ks++) {
        uint32_t ah[2][4], al[2][4], b[2][4];
        ldsm4(ah[0], base + aoff[0][ks]);
        ldsm4(ah[1], base + aoff[1][ks]);
        ldsm4(b[0], base + boff[0][ks]);
        ldsm4(b[1], base + boff[1][ks]);
#pragma unroll
        for (int p = 0; p < 2; p++) {
            mma16816(acc[0][2 * p],     ah[0], b[p][0], b[p][1]);
            mma16816(acc[0][2 * p + 1], ah[0], b[p][2], b[p][3]);
            mma16816(acc[1][2 * p],     ah[1], b[p][0], b[p][1]);
            mma16816(acc[1][2 * p + 1], ah[1], b[p][2], b[p][3]);
        }
        ldsm4(al[0], base + aoff[0][ks] + aLo);
        ldsm4(al[1], base + aoff[1][ks] + aLo);
#pragma unroll
        for (int p = 0; p < 2; p++) {
            mma16816(acc[0][2 * p],     al[0], b[p][0], b[p][1]);
            mma16816(acc[0][2 * p + 1], al[0], b[p][2], b[p][3]);
            mma16816(acc[1][2 * p],     al[1], b[p][0], b[p][1]);
            mma16816(acc[1][2 * p + 1], al[1], b[p][2], b[p][3]);
        }
        ldsm4(b[0], base + boff[0][ks] + bLo);
        ldsm4(b[1], base + boff[1][ks] + bLo);
#pragma unroll
        for (int p = 0; p < 2; p++) {
            mma16816(acc[0][2 * p],     ah[0], b[p][0], b[p][1]);
            mma16816(acc[0][2 * p + 1], ah[0], b[p][2], b[p][3]);
            mma16816(acc[1][2 * p],     ah[1], b[p][0], b[p][1]);
            mma16816(acc[1][2 * p + 1], ah[1], b[p][2], b[p][3]);
        }
    }
}

__device__ __forceinline__ void mk_aoff(uint32_t (&aoff)[2][2], int m_off, int lane,
                                        uint32_t planeA) {
    int sub = lane >> 3, rr = lane & 7;
#pragma unroll
    for (int mi = 0; mi < 2; mi++)
#pragma unroll
        for (int ks = 0; ks < 2; ks++) {
            int row = m_off + mi * 16 + (sub & 1) * 8 + rr;
            int byte = ks * 32 + (sub >> 1) * 16;
            aoff[mi][ks] = planeA + SZ(row * 64 + byte);
        }
}
template <int NP>
__device__ __forceinline__ void mk_boff(uint32_t (&boff)[NP][2], int n_off, int lane,
                                        uint32_t planeB) {
    int sub = lane >> 3, rr = lane & 7;
#pragma unroll
    for (int p = 0; p < NP; p++)
#pragma unroll
        for (int ks = 0; ks < 2; ks++) {
            int row = n_off + p * 16 + (sub >> 1) * 8 + rr;
            int byte = ks * 32 + (sub & 1) * 16;
            boff[p][ks] = planeB + SZ(row * 64 + byte);
        }
}

// ====================== K1: q/k conv =========================================
#define GK_BUF 32768
#define GK_SMEM (2 * GK_BUF)
__global__ void __launch_bounds__(256) k_qk_mma(const float* __restrict__ x,
                                                const float* __restrict__ wq,
                                                const float* __restrict__ wk) {
    extern __shared__ char sm[];
    const int lt = blockIdx.x, qk = blockIdx.y, n = blockIdx.z;
    const float* w = qk ? wk : wq;
    float* outp = qk ? g_kt : g_qt;
    const int l0 = lt * 128;
    uint32_t sb = s2u(sm);
    int t = threadIdx.x, wid = t >> 5, lane = t & 31;
    int wm = wid >> 1, wn = wid & 1;
    int gid = lane >> 2, tig = lane & 3;

    uint32_t aoff[2][2], boff[4][2];
    mk_aoff(aoff, wm * 32, lane, 0u);
    mk_boff<4>(boff, wn * 64, lane, 16384u);

    float acc[2][8][4];
#pragma unroll
    for (int i = 0; i < 2; i++)
#pragma unroll
        for (int j = 0; j < 8; j++)
#pragma unroll
            for (int q = 0; q < 4; q++) acc[i][j][q] = 0.f;

    const int la = t & 127, cg = t >> 7;
    const float* xc = x + (size_t)n * Cc * Ll + l0 + la;

    float sa[4][4];
    float4 sbv[4];

#define K1_LOAD(c0) {                                                          \
    _Pragma("unroll")                                                          \
    for (int it = 0; it < 4; it++) {                                           \
        int ck = (it * 2 + cg) * 4;                                            \
        sa[it][0] = xc[(size_t)((c0) + ck + 0) * Ll];                          \
        sa[it][1] = xc[(size_t)((c0) + ck + 1) * Ll];                          \
        sa[it][2] = xc[(size_t)((c0) + ck + 2) * Ll];                          \
        sa[it][3] = xc[(size_t)((c0) + ck + 3) * Ll];                          \
    }                                                                          \
    _Pragma("unroll")                                                          \
    for (int it = 0; it < 4; it++) {                                           \
        int idx = it * 256 + t;                                                \
        int row = idx >> 3, c4 = (idx & 7) * 4;                                \
        sbv[it] = *(const float4*)&w[(size_t)row * Cc + (c0) + c4];            \
    } }
#define K1_STORE(bsel) {                                                       \
    uint32_t bo = (bsel) * GK_BUF;                                             \
    _Pragma("unroll")                                                          \
    for (int it = 0; it < 4; it++) {                                           \
        int ck = (it * 2 + cg) * 4;                                            \
        uint32_t h0, lo0, h1, lo1;                                             \
        split2(sa[it][0], sa[it][1], h0, lo0);                                 \
        split2(sa[it][2], sa[it][3], h1, lo1);                                 \
        uint32_t off = SZ(la * 64 + ck * 2);                                   \
        *(uint2*)(sm + bo + off)        = make_uint2(h0, h1);                  \
        *(uint2*)(sm + bo + 8192 + off) = make_uint2(lo0, lo1);                \
    }                                                                          \
    _Pragma("unroll")                                                          \
    for (int it = 0; it < 4; it++) {                                           \
        int idx = it * 256 + t;                                                \
        int row = idx >> 3, c4 = (idx & 7) * 4;                                \
        uint32_t h0, lo0, h1, lo1;                                             \
        split2(sbv[it].x, sbv[it].y, h0, lo0);                                 \
        split2(sbv[it].z, sbv[it].w, h1, lo1);                                 \
        uint32_t off = SZ(row * 64 + c4 * 2);                                  \
        *(uint2*)(sm + bo + 16384 + off) = make_uint2(h0, h1);                 \
        *(uint2*)(sm + bo + 24576 + off) = make_uint2(lo0, lo1);               \
    } }

    K1_LOAD(0);
    K1_STORE(0);
    __syncthreads();
#pragma unroll 1
    for (int c = 0; c < 8; c++) {
        if (c + 1 < 8) K1_LOAD((c + 1) * 32);
        chunk_128x128(acc, sb + (c & 1) * GK_BUF, aoff, boff, 8192u, 8192u);
        if (c + 1 < 8) K1_STORE((c + 1) & 1);
        __syncthreads();
    }
#pragma unroll
    for (int mi = 0; mi < 2; mi++)
#pragma unroll
        for (int r2 = 0; r2 < 2; r2++) {
            int l = l0 + wm * 32 + mi * 16 + gid + r2 * 8;
            float* op = outp + ((size_t)(n << 10) + l) * ICc + wn * 64;
#pragma unroll
            for (int nj = 0; nj < 8; nj++)
                *(float2*)&op[nj * 8 + tig * 2] =
                    make_float2(acc[mi][nj][r2 * 2], acc[mi][nj][r2 * 2 + 1]);
        }
}

// ====================== K2: local attention + LN1 stats ======================
__global__ void __launch_bounds__(256) k_attn() {
    int wid = threadIdx.x >> 5;
    int gw = blockIdx.x * 8 + wid;
    int lane = threadIdx.x & 31;
    int n = gw >> 10;
    int l = gw & 1023;
    int h = l >> 5, w = l & 31;
    const float* qp = g_qt + ((size_t)(n << 10) + l) * ICc;
    float4 qv = *(const float4*)&qp[lane * 4];
    float acc[9];
#pragma unroll
    for (int r = 0; r < 9; r++) {
        int hh = h + r / 3 - 1;
        int ww = w + r % 3 - 1;
        float s = 0.f;
        if (hh >= 0 && hh < Hh && ww >= 0 && ww < Ww) {
            const float* kp = g_kt + ((size_t)(n << 10) + (hh << 5) + ww) * ICc;
            float4 kv = *(const float4*)&kp[lane * 4];
            s = qv.x * kv.x + qv.y * kv.y + qv.z * kv.z + qv.w * kv.w;
        }
#pragma unroll
        for (int off = 16; off; off >>= 1) s += __shfl_xor_sync(0xffffffffu, s, off);
        acc[r] = s;
    }
    float val = 0.f;
#pragma unroll
    for (int r = 0; r < 9; r++)
        if (lane == r) val = acc[r];
    if (lane < 9) g_f[(size_t)n * DA + lane * Ll + l] = 2.f * val;

    __shared__ float bs[16];
    if (lane == 0) {
        float s = 0.f, s2 = 0.f;
#pragma unroll
        for (int r = 0; r < 9; r++) {
            float v = 2.f * acc[r];
            s += v; s2 += v * v;
        }
        bs[wid] = s;
        bs[8 + wid] = s2;
    }
    __syncthreads();
    if (threadIdx.x == 0) {
        float S = 0.f, S2 = 0.f;
#pragma unroll
        for (int i = 0; i < 8; i++) { S += bs[i]; S2 += bs[8 + i]; }
        atomicAdd(&g_stats1[n * 2],     S);
        atomicAdd(&g_stats1[n * 2 + 1], S2);
    }
}

// ---------------- init (split into 3 so k_qk_mma is launch #4 for ncu) -------
__global__ void k_z1() { if (threadIdx.x < Nn * 2) g_stats[threadIdx.x] = 0.f; }
__global__ void k_z2() { if (threadIdx.x < Nn * 2) g_stats1[threadIdx.x] = 0.f; }
__global__ void k_z3(const float* __restrict__ b1) {
    int t = blockIdx.x * 256 + threadIdx.x;
    if (t < Nn * Cc) g_h1[t] = b1[t & 255];
}

// ---------------- LN1: normalize only -----------------------------------------
__global__ void __launch_bounds__(256) k_ln1(const float* __restrict__ g1,
                                             const float* __restrict__ be1) {
    int sl = blockIdx.x, n = blockIdx.y, t = threadIdx.x;
    float mu = g_stats1[n * 2] * (1.f / DA);
    float rs = rsqrtf(g_stats1[n * 2 + 1] * (1.f / DA) - mu * mu + EPSf);
    float4* fp4 = (float4*)(g_f + (size_t)n * DA);
    const float4* g4 = (const float4*)g1;
    const float4* b4 = (const float4*)be1;
    int base = sl * 576;
    for (int j = base + t; j < base + 576; j += 256) {
        float4 v = fp4[j];
        float4 gg = g4[j], bb = b4[j];
        v.x = (v.x - mu) * rs * gg.x + bb.x;
        v.y = (v.y - mu) * rs * gg.y + bb.y;
        v.z = (v.z - mu) * rs * gg.z + bb.z;
        v.w = (v.w - mu) * rs * gg.w + bb.w;
        fp4[j] = v;
    }
}

// ---------------- FFN1 split-K ------------------------------------------------
__global__ void __launch_bounds__(256) k_ffn1(const float* __restrict__ w1) {
    int c0 = blockIdx.x * 16;
    int jbase = blockIdx.y * 384;
    __shared__ float fs[32][33];
    __shared__ float ws[16][33];
    int t = threadIdx.x;
    int n = t & 31, cg = t >> 5;
    int c = c0 + cg * 2;
    float acc0 = 0.f, acc1 = 0.f;
    for (int jc = 0; jc < 12; jc++) {
        int j0 = jbase + jc * 32;
        {
            int nn = t >> 3, jj = (t & 7) * 4;
            float4 v = *(const float4*)&g_f[(size_t)nn * DA + j0 + jj];
            fs[nn][jj] = v.x; fs[nn][jj + 1] = v.y; fs[nn][jj + 2] = v.z; fs[nn][jj + 3] = v.w;
        }
        for (int idx = t; idx < 512; idx += 256) {
            int cl = idx >> 5, jj = idx & 31;
            ws[cl][jj] = w1[(size_t)(c0 + cl) * DA + j0 + jj];
        }
        __syncthreads();
#pragma unroll
        for (int jj = 0; jj < 32; jj++) {
            float fv = fs[n][jj];
            acc0 += fv * ws[cg * 2][jj];
            acc1 += fv * ws[cg * 2 + 1][jj];
        }
        __syncthreads();
    }
    atomicAdd(&g_h1[n * Cc + c],     acc0);
    atomicAdd(&g_h1[n * Cc + c + 1], acc1);
}

// ====================== K5: FFN2 + LN2 stats ==================================
#define F2_BUF 36864
#define F2_SMEM (2 * F2_BUF)
__global__ void __launch_bounds__(256) k_ffn2_mma(const float* __restrict__ w2,
                                                  const float* __restrict__ b2) {
    extern __shared__ char sm[];
    const int m0 = blockIdx.x * 256;
    uint32_t sb = s2u(sm);
    int t = threadIdx.x, wid = t >> 5, lane = t & 31;
    int gid = lane >> 2, tig = lane & 3;

    uint32_t aoff[2][2], boff[2][2];
    mk_aoff(aoff, wid * 32, lane, 0u);
    mk_boff<2>(boff, 0, lane, 32768u);

    float acc[2][4][4];
#pragma unroll
    for (int i = 0; i < 2; i++)
#pragma unroll
        for (int j = 0; j < 4; j++)
#pragma unroll
            for (int q = 0; q < 4; q++) acc[i][j][q] = 0.f;

    float4 sav[8];
    float4 sbv;

#define F2_LOAD(c0) {                                                          \
    _Pragma("unroll")                                                          \
    for (int it = 0; it < 8; it++) {                                           \
        int idx = it * 256 + t;                                                \
        int row = idx >> 3, c4 = (idx & 7) * 4;                                \
        sav[it] = *(const float4*)&w2[(size_t)(m0 + row) * Cc + (c0) + c4];    \
    }                                                                          \
    {                                                                          \
        int row = t >> 3, c4 = (t & 7) * 4;                                    \
        float4 v = *(const float4*)&g_h1[(size_t)row * Cc + (c0) + c4];        \
        v.x = fmaxf(v.x, 0.f); v.y = fmaxf(v.y, 0.f);                          \
        v.z = fmaxf(v.z, 0.f); v.w = fmaxf(v.w, 0.f);                          \
        sbv = v;                                                               \
    } }
#define F2_STORE(bsel) {                                                       \
    uint32_t bo = (bsel) * F2_BUF;                                             \
    _Pragma("unroll")                                                          \
    for (int it = 0; it < 8; it++) {                                           \
        int idx = it * 256 + t;                                                \
        int row = idx >> 3, c4 = (idx & 7) * 4;                                \
        uint32_t h0, lo0, h1, lo1;                                             \
        split2(sav[it].x, sav[it].y, h0, lo0);                                 \
        split2(sav[it].z, sav[it].w, h1, lo1);                                 \
        uint32_t off = SZ(row * 64 + c4 * 2);                                  \
        *(uint2*)(sm + bo + off)         = make_uint2(h0, h1);                 \
        *(uint2*)(sm + bo + 16384 + off) = make_uint2(lo0, lo1);               \
    }                                                                          \
    {                                                                          \
        int row = t >> 3, c4 = (t & 7) * 4;                                    \
        uint32_t h0, lo0, h1, lo1;                                             \
        split2(sbv.x, sbv.y, h0, lo0);                                         \
        split2(sbv.z, sbv.w, h1, lo1);                                         \
        uint32_t off = SZ(row * 64 + c4 * 2);                                  \
        *(uint2*)(sm + bo + 32768 + off) = make_uint2(h0, h1);                 \
        *(uint2*)(sm + bo + 34816 + off) = make_uint2(lo0, lo1);               \
    } }

    F2_LOAD(0);
    F2_STORE(0);
    __syncthreads();
#pragma unroll 1
    for (int c = 0; c < 8; c++) {
        if (c + 1 < 8) F2_LOAD((c + 1) * 32);
        chunk_256x32(acc, sb + (c & 1) * F2_BUF, aoff, boff, 16384u, 2048u);
        if (c + 1 < 8) F2_STORE((c + 1) & 1);
        __syncthreads();
    }
    __syncthreads();
    float* ep = (float*)sm;
#pragma unroll
    for (int mi = 0; mi < 2; mi++)
#pragma unroll
        for (int nj = 0; nj < 4; nj++) {
            int m = wid * 32 + mi * 16 + gid;
            int cN = nj * 8 + tig * 2;
            ep[cN * 260 + m]           = acc[mi][nj][0];
            ep[(cN + 1) * 260 + m]     = acc[mi][nj][1];
            ep[cN * 260 + m + 8]       = acc[mi][nj][2];
            ep[(cN + 1) * 260 + m + 8] = acc[mi][nj][3];
        }
    __syncthreads();
#pragma unroll
    for (int it = 0; it < 8; it++) {
        int idx = it * 256 + t;
        int nn = idx >> 6, c4 = (idx & 63) * 4;
        float4 v = *(float4*)&ep[nn * 260 + c4];
        float4 bv = *(const float4*)&b2[m0 + c4];
        v.x += bv.x; v.y += bv.y; v.z += bv.z; v.w += bv.w;
        *(float4*)&g_h2[(size_t)nn * DOUT + m0 + c4] = v;
    }
    // LN2 partial stats: 8 lanes per n
    {
        int nn = t >> 3, seg = t & 7;
        float s = 0.f, s2 = 0.f;
#pragma unroll
        for (int j = seg * 32; j < seg * 32 + 32; j++) {
            float v = ep[nn * 260 + j] + b2[m0 + j];
            s += v; s2 += v * v;
        }
#pragma unroll
        for (int o = 4; o; o >>= 1) {
            s  += __shfl_xor_sync(0xffffffffu, s, o);
            s2 += __shfl_xor_sync(0xffffffffu, s2, o);
        }
        if (seg == 0) {
            atomicAdd(&g_stats[nn * 2],     s);
            atomicAdd(&g_stats[nn * 2 + 1], s2);
        }
    }
}

// ====================== K6: LN2 normalize + transpose into g_qt ===============
__global__ void __launch_bounds__(256) k_ln2t(const float* __restrict__ g2,
                                              const float* __restrict__ be2) {
    __shared__ float ts[64][65];
    int lt = blockIdx.x, ot = blockIdx.y, n = blockIdx.z;
    int l0 = lt * 64, o0 = ot * 64;
    int t = threadIdx.x;
    float mu = g_stats[n * 2] * (1.f / DOUT);
    float rs = rsqrtf(g_stats[n * 2 + 1] * (1.f / DOUT) - mu * mu + EPSf);
    int li = (t & 15) * 4, oi = t >> 4;
#pragma unroll
    for (int p = 0; p < 4; p++) {
        int o = oi + p * 16;
        size_t m = (size_t)(o0 + o) * Ll + l0 + li;
        float4 v = *(const float4*)&g_h2[(size_t)n * DOUT + m];
        float4 gg = *(const float4*)&g2[m];
        float4 bb = *(const float4*)&be2[m];
        ts[li + 0][o] = (v.x - mu) * rs * gg.x + bb.x;
        ts[li + 1][o] = (v.y - mu) * rs * gg.y + bb.y;
        ts[li + 2][o] = (v.z - mu) * rs * gg.z + bb.z;
        ts[li + 3][o] = (v.w - mu) * rs * gg.w + bb.w;
    }
    __syncthreads();
    int oj = (t & 15) * 4, lj = t >> 4;
#pragma unroll
    for (int p = 0; p < 4; p++) {
        int l = lj + p * 16;
        float4 v = make_float4(ts[l][oj], ts[l][oj + 1], ts[l][oj + 2], ts[l][oj + 3]);
        *(float4*)&g_qt[((size_t)(n << 10) + l0 + l) * ICc + o0 + oj] = v;
    }
}

// ====================== K7: out conv + BN + residual ==========================
__global__ void __launch_bounds__(256) k_out_mma(const float* __restrict__ x,
                                                 const float* __restrict__ wout,
                                                 const float* __restrict__ bng,
                                                 const float* __restrict__ bnb,
                                                 const float* __restrict__ bnm,
                                                 const float* __restrict__ bnv,
                                                 float* __restrict__ out) {
    extern __shared__ char sm[];
    const int lt = blockIdx.x, ct = blockIdx.y, n = blockIdx.z;
    const int l0 = lt * 128, c0b = ct * 128;
    uint32_t sb = s2u(sm);
    int t = threadIdx.x, wid = t >> 5, lane = t & 31;
    int wm = wid >> 1, wn = wid & 1;
    int gid = lane >> 2, tig = lane & 3;

    uint32_t aoff[2][2], boff[4][2];
    mk_aoff(aoff, wm * 32, lane, 0u);
    mk_boff<4>(boff, wn * 64, lane, 16384u);

    float acc[2][8][4];
#pragma unroll
    for (int i = 0; i < 2; i++)
#pragma unroll
        for (int j = 0; j < 8; j++)
#pragma unroll
            for (int q = 0; q < 4; q++) acc[i][j][q] = 0.f;

    const float* ytp = g_qt + ((size_t)(n << 10) + l0) * ICc;

    float4 sav[4], sbw[4];

#define K7_LOAD(o0) {                                                          \
    _Pragma("unroll")                                                          \
    for (int it = 0; it < 4; it++) {                                           \
        int idx = it * 256 + t;                                                \
        int row = idx >> 3, c4 = (idx & 7) * 4;                                \
        sav[it] = *(const float4*)&wout[(size_t)(c0b + row) * ICc + (o0) + c4];\
        sbw[it] = *(const float4*)&ytp[(size_t)row * ICc + (o0) + c4];         \
    } }
#define K7_STORE(bsel) {                                                       \
    uint32_t bo = (bsel) * GK_BUF;                                             \
    _Pragma("unroll")                                                          \
    for (int it = 0; it < 4; it++) {                                           \
        int idx = it * 256 + t;                                                \
        int row = idx >> 3, c4 = (idx & 7) * 4;                                \
        uint32_t off = SZ(row * 64 + c4 * 2);                                  \
        uint32_t h0, lo0, h1, lo1;                                             \
        split2(sav[it].x, sav[it].y, h0, lo0);                                 \
        split2(sav[it].z, sav[it].w, h1, lo1);                                 \
        *(uint2*)(sm + bo + off)        = make_uint2(h0, h1);                  \
        *(uint2*)(sm + bo + 8192 + off) = make_uint2(lo0, lo1);                \
        split2(sbw[it].x, sbw[it].y, h0, lo0);                                 \
        split2(sbw[it].z, sbw[it].w, h1, lo1);                                 \
        *(uint2*)(sm + bo + 16384 + off) = make_uint2(h0, h1);                 \
        *(uint2*)(sm + bo + 24576 + off) = make_uint2(lo0, lo1);               \
    } }

    K7_LOAD(0);
    K7_STORE(0);
    __syncthreads();
#pragma unroll 1
    for (int c = 0; c < 4; c++) {
        if (c + 1 < 4) K7_LOAD((c + 1) * 32);
        chunk_128x128(acc, sb + (c & 1) * GK_BUF, aoff, boff, 8192u, 8192u);
        if (c + 1 < 4) K7_STORE((c + 1) & 1);
        __syncthreads();
    }
#pragma unroll
    for (int mi = 0; mi < 2; mi++)
#pragma unroll
        for (int r2 = 0; r2 < 2; r2++) {
            int c = c0b + wm * 32 + mi * 16 + gid + r2 * 8;
            float sc = bng[c] * rsqrtf(bnv[c] + EPSf);
            float mb = bnm[c], bb = bnb[c];
            size_t base = ((size_t)n * Cc + c) * Ll + l0 + wn * 64;
#pragma unroll
            for (int nj = 0; nj < 8; nj++) {
                int lo = nj * 8 + tig * 2;
                float2 xv = *(const float2*)&x[base + lo];
                float2 o;
                o.x = (acc[mi][nj][r2 * 2]     - mb) * sc + bb + xv.x;
                o.y = (acc[mi][nj][r2 * 2 + 1] - mb) * sc + bb + xv.y;
                *(float2*)&out[base + lo] = o;
            }
        }
}

// ---------------- launch -------------------------------------------------------
extern "C" void kernel_launch(void* const* d_in, const int* in_sizes, int n_in,
                              void* d_out, int out_size) {
    const float* x      = (const float*)d_in[0];
    const float* wq     = (const float*)d_in[1];
    const float* wk     = (const float*)d_in[2];
    const float* gamma1 = (const float*)d_in[3];
    const float* beta1  = (const float*)d_in[4];
    const float* w1     = (const float*)d_in[5];
    const float* b1     = (const float*)d_in[6];
    const float* w2     = (const float*)d_in[7];
    const float* b2     = (const float*)d_in[8];
    const float* gamma2 = (const float*)d_in[9];
    const float* beta2  = (const float*)d_in[10];
    const float* w_out  = (const float*)d_in[11];
    const float* bn_g   = (const float*)d_in[12];
    const float* bn_b   = (const float*)d_in[13];
    const float* bn_m   = (const float*)d_in[14];
    const float* bn_v   = (const float*)d_in[15];
    float* out = (float*)d_out;

    cudaFuncSetAttribute(k_qk_mma,   cudaFuncAttributeMaxDynamicSharedMemorySize, GK_SMEM);
    cudaFuncSetAttribute(k_ffn2_mma, cudaFuncAttributeMaxDynamicSharedMemorySize, F2_SMEM);
    cudaFuncSetAttribute(k_out_mma,  cudaFuncAttributeMaxDynamicSharedMemorySize, GK_SMEM);

    k_z1<<<1, 64>>>();
    k_z2<<<1, 64>>>();
    k_z3<<<32, 256>>>(b1);
    k_qk_mma<<<dim3(8, 2, 32), 256, GK_SMEM>>>(x, wq, wk);   // launch #4 -> ncu target
    k_attn<<<4096, 256>>>();
    k_ln1<<<dim3(4, 32), 256>>>(gamma1, beta1);
    k_ffn1<<<dim3(16, 24), 256>>>(w1);
    k_ffn2_mma<<<512, 256, F2_SMEM>>>(w2, b2);
    k_ln2t<<<dim3(16, 2, 32), 256>>>(gamma2, beta2);
    k_out_mma<<<dim3(8, 2, 32), 256, GK_SMEM>>>(x, w_out, bn_g, bn_b, bn_m, bn_v, out);
}